// round 9
// baseline (speedup 1.0000x reference)
#include <cuda_runtime.h>
#include <cstdint>

#define S_LEN 101
#define BATCH 2048
#define HID 200
#define DIN 120
#define DOUT 12
#define M_TOTAL (S_LEN * BATCH)   // 206848

// Scratch (no allocations allowed -> __device__ globals)
__device__ float    g_cur[(size_t)M_TOTAL * HID];     // ~165 MB  cur[b][t][n]
__device__ unsigned g_spk2[(size_t)M_TOTAL * 8];      // ~6.6 MB  spk2[b][t][w]

typedef unsigned long long ull;

// ---------- packed f32x2 helpers (lif kernels) ----------
__device__ __forceinline__ ull pack2(float lo, float hi) {
    ull r; asm("mov.b64 %0, {%1,%2};" : "=l"(r) : "f"(lo), "f"(hi)); return r;
}
__device__ __forceinline__ void unpack2(ull v, float& lo, float& hi) {
    asm("mov.b64 {%0,%1}, %2;" : "=f"(lo), "=f"(hi) : "l"(v));
}
__device__ __forceinline__ ull add2(ull a, ull b) {
    ull d; asm("add.rn.f32x2 %0, %1, %2;" : "=l"(d) : "l"(a), "l"(b)); return d;
}

// ---------- mma / cp.async helpers ----------
__device__ __forceinline__ unsigned tf32of(float x) {
    unsigned u; asm("cvt.rna.tf32.f32 %0, %1;" : "=r"(u) : "f"(x)); return u;
}
__device__ __forceinline__ void mma_tf32(float* c,
                                         unsigned a0, unsigned a1, unsigned a2, unsigned a3,
                                         unsigned b0, unsigned b1) {
    asm volatile(
        "mma.sync.aligned.m16n8k8.row.col.f32.tf32.tf32.f32 "
        "{%0,%1,%2,%3}, {%4,%5,%6,%7}, {%8,%9}, {%0,%1,%2,%3};"
        : "+f"(c[0]), "+f"(c[1]), "+f"(c[2]), "+f"(c[3])
        : "r"(a0), "r"(a1), "r"(a2), "r"(a3), "r"(b0), "r"(b1));
}
__device__ __forceinline__ void ldgsts16(unsigned saddr, const void* gptr) {
    asm volatile("cp.async.cg.shared.global [%0], [%1], 16;" :: "r"(saddr), "l"(gptr));
}
#define CPA_COMMIT() asm volatile("cp.async.commit_group;" ::: "memory")
#define CPA_WAIT1()  asm volatile("cp.async.wait_group 1;" ::: "memory")

// ================= Kernel 1: CUR1 = X @ W1 + b1 via mma.sync TF32 3x-split ===
// Even CTAs: cols 0..103 (13 n-frags); odd CTAs: cols 104..199 (12 n-frags).
// 512 threads / 16 warps: warp = (m-frag warp>>1, n-half warp&1) -> <=7 frags
// per warp (4 warps/SMSP for latency hiding; acc regs 28/thread).
#define GM_THREADS 512
#define NFMAX 13
#define NFW 7
#define GM_STR 124
#define GM_STG (128 * GM_STR)                          // floats per stage buffer
#define BF_BYTES (15 * NFMAX * 32 * 16)                // 99840
#define GM_SMEM (BF_BYTES + 2 * GM_STG * 4)            // 226816 B
#define MTILES (M_TOTAL / 128)                         // 1616

__global__ __launch_bounds__(GM_THREADS, 1)
void gemm1_mma_kernel(const float* __restrict__ x,
                      const float* __restrict__ W1,
                      const float* __restrict__ b1) {
    extern __shared__ char sm[];
    float4* Bf  = (float4*)sm;                         // [15][13][32]
    float*  As0 = (float*)(sm + BF_BYTES);             // [128][124]
    float*  As1 = As0 + GM_STG;

    const int tid   = threadIdx.x;
    const int warp  = tid >> 5;
    const int lane  = tid & 31;
    const int group = lane >> 2;       // 0..7
    const int tg    = lane & 3;        // 0..3
    const int mf    = warp >> 1;       // m-fragment 0..7 (rows mf*16..+15)
    const int nh    = warp & 1;        // n-half
    const int half  = blockIdx.x & 1;
    const int colbase = half ? 104 : 0;
    const int nfc     = half ? 12 : 13;                // n-frags in this CTA
    const int nfsplit = (nfc + 1) >> 1;
    const int nf0     = nh ? nfsplit : 0;              // this warp's first frag
    const int nfcw    = nh ? nfc - nfsplit : nfsplit;  // frags this warp (<=7)

    const unsigned sA0 = (unsigned)__cvta_generic_to_shared(As0);
    const unsigned sA1 = (unsigned)__cvta_generic_to_shared(As1);

    // issue cp.async loads for one tile into one stage buffer (x gather)
    auto issue_stage = [&](int mt, unsigned sbase) {
        if (mt < MTILES) {
            const int row0 = mt * 128;
            for (int i = tid; i < 128 * 30; i += GM_THREADS) {
                int r = i / 30, cs = i - r * 30;
                int c = cs / 10, j = cs - c * 10;
                int row = row0 + r;
                int b = row / S_LEN, t = row - b * S_LEN;
                const float* gp = x + ((size_t)((b * 3 + c) * S_LEN + t)) * 40 + j * 4;
                unsigned sp = sbase + (unsigned)((r * GM_STR + c * 40 + j * 4) * 4);
                ldgsts16(sp, gp);
            }
        }
        CPA_COMMIT();
    };

    int m = blockIdx.x >> 1;
    issue_stage(m, sA0);               // group 0 in flight while we build Bf

    // ---- pre-split B = W1 half into fragment-native hi/lo layout ----
    // Bf[ks][nf][t] = {b0hi, b1hi, b0lo, b1lo};  b0 = W1[8ks+tg][n], b1 = +4 k
    for (int idx = tid; idx < 15 * nfc * 32; idx += GM_THREADS) {
        int ks  = idx / (nfc * 32);
        int rem = idx - ks * nfc * 32;
        int nf  = rem >> 5;
        int t   = rem & 31;
        int g = t >> 2, q = t & 3;
        int k = ks * 8 + q;
        int n = colbase + nf * 8 + g;
        float w0 = W1[k * HID + n];
        float w1 = W1[(k + 4) * HID + n];
        unsigned h0 = tf32of(w0), h1 = tf32of(w1);
        unsigned l0 = tf32of(w0 - __uint_as_float(h0));
        unsigned l1 = tf32of(w1 - __uint_as_float(h1));
        Bf[(ks * NFMAX + nf) * 32 + t] =
            make_float4(__uint_as_float(h0), __uint_as_float(h1),
                        __uint_as_float(l0), __uint_as_float(l1));
    }

    // bias per accumulator column pair: col = colbase + (nf0+nf)*8 + 2*tg (+1)
    float2 bias[NFW];
    #pragma unroll
    for (int nf = 0; nf < NFW; nf++) {
        if (nf < nfcw) {
            int c = colbase + (nf0 + nf) * 8 + 2 * tg;
            bias[nf] = make_float2(b1[c], b1[c + 1]);
        } else bias[nf] = make_float2(0.f, 0.f);
    }

    int idx = 0;
    for (; m < MTILES; m += 74, idx ^= 1) {
        issue_stage(m + 74, idx ? sA0 : sA1);          // prefetch next
        CPA_WAIT1();                                   // current stage ready
        __syncthreads();                               // + Bf visible (1st iter)

        const float* As = idx ? As1 : As0;
        const float* arow = As + (mf * 16 + group) * GM_STR;

        float acc[NFW][4];
        #pragma unroll
        for (int nf = 0; nf < NFW; nf++) {
            acc[nf][0] = bias[nf].x; acc[nf][1] = bias[nf].y;
            acc[nf][2] = bias[nf].x; acc[nf][3] = bias[nf].y;
        }

        #pragma unroll
        for (int ks = 0; ks < 15; ks++) {
            const int k0 = ks * 8;
            float a0 = arow[k0 + tg];
            float a2 = arow[k0 + tg + 4];
            float a1 = arow[8 * GM_STR + k0 + tg];
            float a3 = arow[8 * GM_STR + k0 + tg + 4];
            unsigned ah0 = tf32of(a0), ah1 = tf32of(a1),
                     ah2 = tf32of(a2), ah3 = tf32of(a3);
            unsigned al0 = tf32of(a0 - __uint_as_float(ah0));
            unsigned al1 = tf32of(a1 - __uint_as_float(ah1));
            unsigned al2 = tf32of(a2 - __uint_as_float(ah2));
            unsigned al3 = tf32of(a3 - __uint_as_float(ah3));

            const float4* bp = Bf + ks * NFMAX * 32 + nf0 * 32 + lane;
            #pragma unroll
            for (int nf = 0; nf < NFW; nf++) {
                if (nf < nfcw) {
                    float4 b = bp[nf * 32];                       // LDS.128
                    unsigned bh0 = __float_as_uint(b.x), bh1 = __float_as_uint(b.y);
                    unsigned bl0 = __float_as_uint(b.z), bl1 = __float_as_uint(b.w);
                    mma_tf32(acc[nf], ah0, ah1, ah2, ah3, bh0, bh1);   // hi*hi
                    mma_tf32(acc[nf], ah0, ah1, ah2, ah3, bl0, bl1);   // hi*lo
                    mma_tf32(acc[nf], al0, al1, al2, al3, bh0, bh1);   // lo*hi
                }
            }
        }

        // epilogue: c0/c1 at (row=mf*16+group, col=(nf0+nf)*8+2tg), c2/c3 row+8
        const int r0 = m * 128 + mf * 16 + group;
        float* op = g_cur + (size_t)r0 * HID + colbase + nf0 * 8;
        #pragma unroll
        for (int nf = 0; nf < NFW; nf++) {
            if (nf < nfcw) {
                *(float2*)(op + nf * 8 + 2 * tg) =
                    make_float2(acc[nf][0], acc[nf][1]);
                *(float2*)(op + 8 * HID + nf * 8 + 2 * tg) =
                    make_float2(acc[nf][2], acc[nf][3]);
            }
        }
        __syncthreads();   // next iter's cp.async overwrites the buffer just read
    }
}

// ================= LIF kernels (unchanged from R5/R6) ========================
#define L_GROUPS 14
#define GW 64
#define L_THREADS (L_GROUPS * GW)               // 896
#define W_SMEM (HID * HID * 4)                  // 160000 B

__device__ __forceinline__ void group_bar(int grp) {
    asm volatile("bar.sync %0, %1;" :: "r"(grp + 1), "r"(GW) : "memory");
}

__device__ __forceinline__ void scan4(const unsigned* words, const float4* Ws4,
                                      int i, ull& accA, ull& accB) {
    #pragma unroll
    for (int m = 0; m < 8; m++) {
        unsigned u = words[m];
        const int base = ((m >> 2) << 7) + (m & 3);
        while (u) {                                   // uniform among active lanes
            int j = __ffs(u) - 1;
            u &= u - 1;
            int h = base + (j << 2);
            float4 wv = Ws4[h * 50 + i];
            accA = add2(accA, pack2(wv.x, wv.y));
            accB = add2(accB, pack2(wv.z, wv.w));
        }
    }
}

__global__ __launch_bounds__(L_THREADS, 1)
void lif2_kernel(const float* __restrict__ W2, const float* __restrict__ b2) {
    extern __shared__ float smem[];
    const float4* Ws4 = (const float4*)smem;           // [200][50] float4
    __shared__ unsigned sw[2][L_GROUPS][8];
    const int tid = threadIdx.x;
    for (int k = tid; k < HID * HID; k += L_THREADS) smem[k] = W2[k];

    const int  grp  = tid / GW;
    const int  i    = tid - grp * GW;      // 0..63
    const int  lane = i & 31;
    const int  wig  = i >> 5;              // warp in group (0,1)
    const bool iv   = (i < 50);            // active: neurons 4i..4i+3
    float4 bias = make_float4(0.f, 0.f, 0.f, 0.f);
    if (iv) bias = *(const float4*)(b2 + 4 * i);
    __syncthreads();

    for (int b = blockIdx.x * L_GROUPS + grp; b < BATCH; b += gridDim.x * L_GROUPS) {
        float v10 = 0.f, v11 = 0.f, v12 = 0.f, v13 = 0.f;
        float v20 = 0.f, v21 = 0.f, v22 = 0.f, v23 = 0.f;
        const float4* curp = (const float4*)(g_cur + (size_t)b * S_LEN * HID) + (iv ? i : 0);
        unsigned*     spk  = g_spk2 + (size_t)b * S_LEN * 8;

        const int P = 4;
        float4 buf[P];
        #pragma unroll
        for (int q = 0; q < P; q++) buf[q] = iv ? curp[q * 50] : make_float4(0,0,0,0);

        for (int t = 0; t < S_LEN; t++) {
            float4 cur = buf[t & (P - 1)];
            int tp = t + P; if (tp > S_LEN - 1) tp = S_LEN - 1;
            if (iv) buf[t & (P - 1)] = curp[tp * 50];   // prefetch (indep of v)

            v10 = 0.5f * (v10 + cur.x); v11 = 0.5f * (v11 + cur.y);
            v12 = 0.5f * (v12 + cur.z); v13 = 0.5f * (v13 + cur.w);
            bool s0 = iv && (v10 >= 1.0f); if (s0) v10 = 0.f;
            bool s1 = iv && (v11 >= 1.0f); if (s1) v11 = 0.f;
            bool s2 = iv && (v12 >= 1.0f); if (s2) v12 = 0.f;
            bool s3 = iv && (v13 >= 1.0f); if (s3) v13 = 0.f;
            unsigned m0 = __ballot_sync(0xffffffffu, s0);
            unsigned m1 = __ballot_sync(0xffffffffu, s1);
            unsigned m2 = __ballot_sync(0xffffffffu, s2);
            unsigned m3 = __ballot_sync(0xffffffffu, s3);
            if (lane == 0) {
                unsigned* swp = sw[t & 1][grp] + 4 * wig;
                swp[0] = m0; swp[1] = m1; swp[2] = m2; swp[3] = m3;
            }
            group_bar(grp);

            ull accA = pack2(bias.x, bias.y), accB = pack2(bias.z, bias.w);
            if (iv) scan4(sw[t & 1][grp], Ws4, i, accA, accB);
            float a0, a1, a2, a3;
            unpack2(accA, a0, a1); unpack2(accB, a2, a3);

            v20 = 0.5f * (v20 + a0); v21 = 0.5f * (v21 + a1);
            v22 = 0.5f * (v22 + a2); v23 = 0.5f * (v23 + a3);
            bool r0 = iv && (v20 >= 1.0f); if (r0) v20 = 0.f;
            bool r1 = iv && (v21 >= 1.0f); if (r1) v21 = 0.f;
            bool r2 = iv && (v22 >= 1.0f); if (r2) v22 = 0.f;
            bool r3 = iv && (v23 >= 1.0f); if (r3) v23 = 0.f;
            unsigned n0 = __ballot_sync(0xffffffffu, r0);
            unsigned n1 = __ballot_sync(0xffffffffu, r1);
            unsigned n2 = __ballot_sync(0xffffffffu, r2);
            unsigned n3 = __ballot_sync(0xffffffffu, r3);
            if (lane == 0) {
                unsigned* sp = spk + (size_t)t * 8 + 4 * wig;
                sp[0] = n0; sp[1] = n1; sp[2] = n2; sp[3] = n3;
            }
        }
    }
}

__global__ __launch_bounds__(L_THREADS, 1)
void lif3_kernel(const float* __restrict__ W3, const float* __restrict__ b3,
                 const float* __restrict__ Wr, const float* __restrict__ br,
                 float* __restrict__ out) {
    extern __shared__ float smem[];
    const float4* Ws4 = (const float4*)smem;
    __shared__ float cnt_sm[L_GROUPS][HID];
    const int tid = threadIdx.x;
    for (int k = tid; k < HID * HID; k += L_THREADS) smem[k] = W3[k];

    const int  grp  = tid / GW;
    const int  i    = tid - grp * GW;
    const int  lane = i & 31;
    const int  wig  = i >> 5;
    const bool iv   = (i < 50);
    float4 bias = make_float4(0.f, 0.f, 0.f, 0.f);
    if (iv) bias = *(const float4*)(b3 + 4 * i);
    __syncthreads();

    for (int b = blockIdx.x * L_GROUPS + grp; b < BATCH; b += gridDim.x * L_GROUPS) {
        float v30 = 0.f, v31 = 0.f, v32 = 0.f, v33 = 0.f;
        int c0 = 0, c1 = 0, c2 = 0, c3 = 0;
        const unsigned* sp = g_spk2 + (size_t)b * S_LEN * 8;

        unsigned curm[8];
        #pragma unroll
        for (int w = 0; w < 8; w++) curm[w] = __ldg(sp + w);

        for (int t = 0; t < S_LEN; t++) {
            unsigned nxtm[8];
            const unsigned* spn = sp + (size_t)((t + 1 < S_LEN) ? t + 1 : t) * 8;
            #pragma unroll
            for (int w = 0; w < 8; w++) nxtm[w] = __ldg(spn + w);   // prefetch

            ull accA = pack2(bias.x, bias.y), accB = pack2(bias.z, bias.w);
            if (iv) scan4(curm, Ws4, i, accA, accB);
            float a0, a1, a2, a3;
            unpack2(accA, a0, a1); unpack2(accB, a2, a3);

            v30 = 0.5f * (v30 + a0); if (v30 >= 1.0f) { v30 = 0.f; c0++; }
            v31 = 0.5f * (v31 + a1); if (v31 >= 1.0f) { v31 = 0.f; c1++; }
            v32 = 0.5f * (v32 + a2); if (v32 >= 1.0f) { v32 = 0.f; c2++; }
            v33 = 0.5f * (v33 + a3); if (v33 >= 1.0f) { v33 = 0.f; c3++; }
            #pragma unroll
            for (int w = 0; w < 8; w++) curm[w] = nxtm[w];
        }
        if (iv)
            *(float4*)&cnt_sm[grp][4 * i] =
                make_float4((float)c0, (float)c1, (float)c2, (float)c3);
        group_bar(grp);

        if (wig == 0) {                    // warp 0 of group: readout for this b
            float o = -3.0e38f;
            if (lane < DOUT) {
                float acc = 0.f;
                #pragma unroll 4
                for (int k = 0; k < HID; k++)
                    acc += cnt_sm[grp][k] * Wr[k * DOUT + lane];
                o = acc * (1.0f / 101.0f) + br[lane];
            }
            float m = o;
            #pragma unroll
            for (int off = 16; off; off >>= 1)
                m = fmaxf(m, __shfl_xor_sync(0xffffffffu, m, off));
            float e = (lane < DOUT) ? expf(o - m) : 0.f;
            float ssum = e;
            #pragma unroll
            for (int off = 16; off; off >>= 1)
                ssum += __shfl_xor_sync(0xffffffffu, ssum, off);
            if (lane < DOUT) out[b * DOUT + lane] = (o - m) - logf(ssum);
        }
        group_bar(grp);                    // protect cnt_sm before next b iter
    }
}

// ================= launch ====================================================
extern "C" void kernel_launch(void* const* d_in, const int* in_sizes, int n_in,
                              void* d_out, int out_size) {
    const float* x  = (const float*)d_in[0];
    const float* W1 = (const float*)d_in[1];
    const float* b1 = (const float*)d_in[2];
    const float* W2 = (const float*)d_in[3];
    const float* b2 = (const float*)d_in[4];
    const float* W3 = (const float*)d_in[5];
    const float* b3 = (const float*)d_in[6];
    const float* Wr = (const float*)d_in[7];
    const float* br = (const float*)d_in[8];
    float* out = (float*)d_out;

    cudaFuncSetAttribute(gemm1_mma_kernel, cudaFuncAttributeMaxDynamicSharedMemorySize, GM_SMEM);
    cudaFuncSetAttribute(lif2_kernel,      cudaFuncAttributeMaxDynamicSharedMemorySize, W_SMEM);
    cudaFuncSetAttribute(lif3_kernel,      cudaFuncAttributeMaxDynamicSharedMemorySize, W_SMEM);

    const int grid = 148;

    gemm1_mma_kernel<<<grid, GM_THREADS, GM_SMEM>>>(x, W1, b1);
    lif2_kernel    <<<grid, L_THREADS,   W_SMEM>>>(W2, b2);
    lif3_kernel    <<<grid, L_THREADS,   W_SMEM>>>(W3, b3, Wr, br, out);
}

// round 10
// speedup vs baseline: 1.2973x; 1.2973x over previous
#include <cuda_runtime.h>
#include <cstdint>

#define S_LEN 101
#define BATCH 2048
#define HID 200
#define DIN 120
#define DOUT 12
#define M_TOTAL (S_LEN * BATCH)   // 206848

// Scratch (no allocations allowed -> __device__ globals)
__device__ float    g_cur[(size_t)M_TOTAL * HID];     // ~165 MB  cur[b][t][n]
__device__ unsigned g_spk2[(size_t)M_TOTAL * 8];      // masks: word m, bit j -> neuron 8j+m

typedef unsigned long long ull;

// ---------- packed f32x2 helpers ----------
__device__ __forceinline__ ull pack2(float lo, float hi) {
    ull r; asm("mov.b64 %0, {%1,%2};" : "=l"(r) : "f"(lo), "f"(hi)); return r;
}
__device__ __forceinline__ void unpack2(ull v, float& lo, float& hi) {
    asm("mov.b64 {%0,%1}, %2;" : "=f"(lo), "=f"(hi) : "l"(v));
}
__device__ __forceinline__ ull add2(ull a, ull b) {
    ull d; asm("add.rn.f32x2 %0, %1, %2;" : "=l"(d) : "l"(a), "l"(b)); return d;
}

// ---------- bf16 / mma / cp.async helpers ----------
__device__ __forceinline__ unsigned bf16x2of(float lo, float hi) {
    unsigned r; asm("cvt.rn.bf16x2.f32 %0, %1, %2;" : "=r"(r) : "f"(hi), "f"(lo));
    return r;   // lo -> bits[0:16), hi -> bits[16:32)
}
__device__ __forceinline__ void bf16_hilo(float x0, float x1, unsigned& h, unsigned& l) {
    h = bf16x2of(x0, x1);
    float h0 = __uint_as_float(h << 16);
    float h1 = __uint_as_float(h & 0xffff0000u);
    l = bf16x2of(x0 - h0, x1 - h1);
}
__device__ __forceinline__ void mma_bf16(float* c,
                                         unsigned a0, unsigned a1, unsigned a2, unsigned a3,
                                         unsigned b0, unsigned b1) {
    asm volatile(
        "mma.sync.aligned.m16n8k16.row.col.f32.bf16.bf16.f32 "
        "{%0,%1,%2,%3}, {%4,%5,%6,%7}, {%8,%9}, {%0,%1,%2,%3};"
        : "+f"(c[0]), "+f"(c[1]), "+f"(c[2]), "+f"(c[3])
        : "r"(a0), "r"(a1), "r"(a2), "r"(a3), "r"(b0), "r"(b1));
}
__device__ __forceinline__ void ldgsts16(unsigned saddr, const void* gptr) {
    asm volatile("cp.async.cg.shared.global [%0], [%1], 16;" :: "r"(saddr), "l"(gptr));
}
#define CPA_COMMIT() asm volatile("cp.async.commit_group;" ::: "memory")
#define CPA_WAIT1()  asm volatile("cp.async.wait_group 1;" ::: "memory")

// ================= Kernel 1: CUR1 = X @ W1 + b1, BF16 3x-split mma.sync ======
// R8 mapping: 256 threads / 8 warps, warp = m-frag (16 rows), owns all n-frags.
// Even CTAs: cols 0..103 (13 frags); odd: 104..199 (12). K=120 padded to 128
// (8 k-steps of 16); pad zeros live in the smem stage + zero B rows.
#define GM_THREADS 256
#define NFMAX 13
#define GM_STR 136
#define GM_STG (128 * GM_STR)                          // floats per stage buffer
#define BF_BYTES (8 * NFMAX * 32 * 16)                 // 53248
#define GM_SMEM (BF_BYTES + 2 * GM_STG * 4)            // 192512 B
#define MTILES (M_TOTAL / 128)                         // 1616

__global__ __launch_bounds__(GM_THREADS, 1)
void gemm1_mma_kernel(const float* __restrict__ x,
                      const float* __restrict__ W1,
                      const float* __restrict__ b1) {
    extern __shared__ char sm[];
    uint4* Bf  = (uint4*)sm;                           // [8][13][32]
    float* As0 = (float*)(sm + BF_BYTES);              // [128][136]
    float* As1 = As0 + GM_STG;

    const int tid   = threadIdx.x;
    const int warp  = tid >> 5;
    const int lane  = tid & 31;
    const int group = lane >> 2;       // 0..7
    const int tg    = lane & 3;        // 0..3
    const int half  = blockIdx.x & 1;
    const int colbase = half ? 104 : 0;
    const int nfc     = half ? 12 : 13;

    const unsigned sA0 = (unsigned)__cvta_generic_to_shared(As0);
    const unsigned sA1 = (unsigned)__cvta_generic_to_shared(As1);

    auto issue_stage = [&](int mt, unsigned sbase) {
        if (mt < MTILES) {
            const int row0 = mt * 128;
            for (int i = tid; i < 128 * 30; i += GM_THREADS) {
                int r = i / 30, cs = i - r * 30;
                int c = cs / 10, j = cs - c * 10;
                int row = row0 + r;
                int b = row / S_LEN, t = row - b * S_LEN;
                const float* gp = x + ((size_t)((b * 3 + c) * S_LEN + t)) * 40 + j * 4;
                unsigned sp = sbase + (unsigned)((r * GM_STR + c * 40 + j * 4) * 4);
                ldgsts16(sp, gp);
            }
        }
        CPA_COMMIT();
    };

    int m = blockIdx.x >> 1;
    issue_stage(m, sA0);

    // zero-pad k=120..127 in both stage buffers (cp.async never writes these)
    for (int i = tid; i < 128 * 8 * 2; i += GM_THREADS) {
        int buf = i >> 10, r = (i >> 3) & 127, w = i & 7;
        (buf ? As1 : As0)[r * GM_STR + 120 + w] = 0.f;
    }

    // ---- pre-split B = W1 half -> fragment-native bf16 hi/lo layout ----
    // Bf[ks][nf][t] = {b0hi, b1hi, b0lo, b1lo}
    // b0 = W[16ks+2q .. +1][n], b1 = W[16ks+2q+8 .. +9][n]; n = colbase+8nf+g
    for (int idx = tid; idx < 8 * nfc * 32; idx += GM_THREADS) {
        int ks  = idx / (nfc * 32);
        int rem = idx - ks * nfc * 32;
        int nf  = rem >> 5;
        int t   = rem & 31;
        int g = t >> 2, q = t & 3;
        int n  = colbase + nf * 8 + g;
        int k0 = ks * 16 + 2 * q;
        int k1 = k0 + 8;
        float w00 = W1[k0 * HID + n];
        float w01 = W1[(k0 + 1) * HID + n];
        float w10 = (k1     < DIN) ? W1[k1 * HID + n]       : 0.f;
        float w11 = (k1 + 1 < DIN) ? W1[(k1 + 1) * HID + n] : 0.f;
        unsigned b0h, b0l, b1h, b1l;
        bf16_hilo(w00, w01, b0h, b0l);
        bf16_hilo(w10, w11, b1h, b1l);
        Bf[(ks * NFMAX + nf) * 32 + t] = make_uint4(b0h, b1h, b0l, b1l);
    }

    float2 bias[NFMAX];
    #pragma unroll
    for (int nf = 0; nf < NFMAX; nf++) {
        if (nf < nfc) {
            int c = colbase + nf * 8 + 2 * tg;
            bias[nf] = make_float2(b1[c], b1[c + 1]);
        } else bias[nf] = make_float2(0.f, 0.f);
    }

    int idx = 0;
    for (; m < MTILES; m += 74, idx ^= 1) {
        issue_stage(m + 74, idx ? sA0 : sA1);          // prefetch next
        CPA_WAIT1();                                   // current stage ready
        __syncthreads();                               // + Bf/pad visible (1st iter)

        const float* As = idx ? As1 : As0;
        const float* arow  = As + (warp * 16 + group) * GM_STR;
        const float* arow8 = arow + 8 * GM_STR;

        float acc[NFMAX][4];
        #pragma unroll
        for (int nf = 0; nf < NFMAX; nf++) {
            acc[nf][0] = bias[nf].x; acc[nf][1] = bias[nf].y;
            acc[nf][2] = bias[nf].x; acc[nf][3] = bias[nf].y;
        }

        #pragma unroll
        for (int ks = 0; ks < 8; ks++) {
            const int k0 = ks * 16 + 2 * tg;
            float2 p0 = *(const float2*)(arow  + k0);      // a0: row g,   k k0..+1
            float2 p1 = *(const float2*)(arow8 + k0);      // a1: row g+8
            float2 p2 = *(const float2*)(arow  + k0 + 8);  // a2: row g,   k+8
            float2 p3 = *(const float2*)(arow8 + k0 + 8);  // a3: row g+8, k+8
            unsigned ah0, al0, ah1, al1, ah2, al2, ah3, al3;
            bf16_hilo(p0.x, p0.y, ah0, al0);
            bf16_hilo(p1.x, p1.y, ah1, al1);
            bf16_hilo(p2.x, p2.y, ah2, al2);
            bf16_hilo(p3.x, p3.y, ah3, al3);

            const uint4* bp = Bf + ks * NFMAX * 32 + lane;
            #pragma unroll
            for (int nf = 0; nf < NFMAX; nf++) {
                if (nf < nfc) {
                    uint4 b = bp[nf * 32];                        // LDS.128
                    mma_bf16(acc[nf], ah0, ah1, ah2, ah3, b.x, b.y);   // hi*hi
                    mma_bf16(acc[nf], ah0, ah1, ah2, ah3, b.z, b.w);   // hi*lo
                    mma_bf16(acc[nf], al0, al1, al2, al3, b.x, b.y);   // lo*hi
                }
            }
        }

        const int r0 = m * 128 + warp * 16 + group;
        float* op = g_cur + (size_t)r0 * HID + colbase;
        #pragma unroll
        for (int nf = 0; nf < NFMAX; nf++) {
            if (nf < nfc) {
                *(float2*)(op + nf * 8 + 2 * tg) =
                    make_float2(acc[nf][0], acc[nf][1]);
                *(float2*)(op + 8 * HID + nf * 8 + 2 * tg) =
                    make_float2(acc[nf][2], acc[nf][3]);
            }
        }
        __syncthreads();
    }
}

// ================= LIF kernels: 1-warp groups, no barriers ===================
// 14 groups of 32 threads per CTA; 148*14 = 2072 >= 2048 -> one b per group.
// Thread lane (lane<25) owns neurons 8*lane..8*lane+7.
// Mask word m (0..7): bit j -> neuron 8j+m.
#define L_GROUPS 14
#define GW 32
#define L_THREADS (L_GROUPS * GW)               // 448
#define W_SMEM (HID * HID * 4)                  // 160000 B

// Warp-uniform sparse scan over 8 mask words; 8 cols per thread via 2x LDS.128.
__device__ __forceinline__ void scan8(const unsigned* mk, const float4* Wp,
                                      ull* acc) {
    #pragma unroll
    for (int m = 0; m < 8; m++) {
        unsigned u = mk[m];
        while (u) {                                   // uniform across warp
            int j = __ffs(u) - 1;
            u &= u - 1;
            int h = 8 * j + m;
            float4 w0 = Wp[h * 50];
            float4 w1 = Wp[h * 50 + 1];
            acc[0] = add2(acc[0], pack2(w0.x, w0.y));
            acc[1] = add2(acc[1], pack2(w0.z, w0.w));
            acc[2] = add2(acc[2], pack2(w1.x, w1.y));
            acc[3] = add2(acc[3], pack2(w1.z, w1.w));
        }
    }
}

__global__ __launch_bounds__(L_THREADS, 1)
void lif2_kernel(const float* __restrict__ W2, const float* __restrict__ b2) {
    extern __shared__ float smem[];
    const float4* Ws4 = (const float4*)smem;           // [200][50] float4
    const int tid  = threadIdx.x;
    const int grp  = tid >> 5;
    const int lane = tid & 31;
    for (int k = tid; k < HID * HID; k += L_THREADS) smem[k] = W2[k];

    const bool iv = (lane < 25);
    const float4* Wp = Ws4 + (iv ? 2 * lane : 0);
    float4 biasA = make_float4(0,0,0,0), biasB = make_float4(0,0,0,0);
    if (iv) { biasA = *(const float4*)(b2 + 8 * lane);
              biasB = *(const float4*)(b2 + 8 * lane + 4); }
    __syncthreads();

    const int b = blockIdx.x * L_GROUPS + grp;
    if (b >= BATCH) return;                            // warp-uniform

    float v1[8], v2[8];
    #pragma unroll
    for (int e = 0; e < 8; e++) { v1[e] = 0.f; v2[e] = 0.f; }
    const float* curb = g_cur + (size_t)b * S_LEN * HID + (iv ? 8 * lane : 0);
    unsigned* spk = g_spk2 + (size_t)b * S_LEN * 8;

    float4 bufA[4], bufB[4];
    #pragma unroll
    for (int q = 0; q < 4; q++) {
        bufA[q] = *(const float4*)(curb + q * HID);
        bufB[q] = *(const float4*)(curb + q * HID + 4);
    }

    for (int t = 0; t < S_LEN; t++) {
        float a[8];
        { float4 ca = bufA[t & 3], cb = bufB[t & 3];
          a[0]=ca.x; a[1]=ca.y; a[2]=ca.z; a[3]=ca.w;
          a[4]=cb.x; a[5]=cb.y; a[6]=cb.z; a[7]=cb.w; }
        int tp = t + 4; if (tp > S_LEN - 1) tp = S_LEN - 1;
        bufA[t & 3] = *(const float4*)(curb + (size_t)tp * HID);
        bufB[t & 3] = *(const float4*)(curb + (size_t)tp * HID + 4);

        unsigned mk[8];
        #pragma unroll
        for (int e = 0; e < 8; e++) {
            v1[e] = 0.5f * (v1[e] + a[e]);
            bool s = iv && (v1[e] >= 1.0f);
            if (s) v1[e] = 0.f;
            mk[e] = __ballot_sync(0xffffffffu, s);
        }

        ull acc[4] = { pack2(biasA.x, biasA.y), pack2(biasA.z, biasA.w),
                       pack2(biasB.x, biasB.y), pack2(biasB.z, biasB.w) };
        scan8(mk, Wp, acc);
        float c[8];
        unpack2(acc[0], c[0], c[1]); unpack2(acc[1], c[2], c[3]);
        unpack2(acc[2], c[4], c[5]); unpack2(acc[3], c[6], c[7]);

        unsigned nk[8];
        #pragma unroll
        for (int e = 0; e < 8; e++) {
            v2[e] = 0.5f * (v2[e] + c[e]);
            bool s = iv && (v2[e] >= 1.0f);
            if (s) v2[e] = 0.f;
            nk[e] = __ballot_sync(0xffffffffu, s);
        }
        if (lane == 0) {
            *(uint4*)(spk + (size_t)t * 8)     = make_uint4(nk[0], nk[1], nk[2], nk[3]);
            *(uint4*)(spk + (size_t)t * 8 + 4) = make_uint4(nk[4], nk[5], nk[6], nk[7]);
        }
    }
}

__global__ __launch_bounds__(L_THREADS, 1)
void lif3_kernel(const float* __restrict__ W3, const float* __restrict__ b3,
                 const float* __restrict__ Wr, const float* __restrict__ br,
                 float* __restrict__ out) {
    extern __shared__ float smem[];
    const float4* Ws4 = (const float4*)smem;
    __shared__ float cnt_sm[L_GROUPS][HID];
    const int tid  = threadIdx.x;
    const int grp  = tid >> 5;
    const int lane = tid & 31;
    for (int k = tid; k < HID * HID; k += L_THREADS) smem[k] = W3[k];

    const bool iv = (lane < 25);
    const float4* Wp = Ws4 + (iv ? 2 * lane : 0);
    float4 biasA = make_float4(0,0,0,0), biasB = make_float4(0,0,0,0);
    if (iv) { biasA = *(const float4*)(b3 + 8 * lane);
              biasB = *(const float4*)(b3 + 8 * lane + 4); }
    __syncthreads();

    const int b = blockIdx.x * L_GROUPS + grp;
    if (b >= BATCH) return;                            // warp-uniform

    float v3[8];
    int cnt[8];
    #pragma unroll
    for (int e = 0; e < 8; e++) { v3[e] = 0.f; cnt[e] = 0; }
    const uint4* sp = (const uint4*)(g_spk2 + (size_t)b * S_LEN * 8);

    uint4 ca = sp[0], cb = sp[1];                      // broadcast loads
    for (int t = 0; t < S_LEN; t++) {
        int tp = (t + 1 < S_LEN) ? t + 1 : t;
        uint4 na = sp[tp * 2], nb = sp[tp * 2 + 1];    // prefetch

        unsigned mk[8] = { ca.x, ca.y, ca.z, ca.w, cb.x, cb.y, cb.z, cb.w };
        ull acc[4] = { pack2(biasA.x, biasA.y), pack2(biasA.z, biasA.w),
                       pack2(biasB.x, biasB.y), pack2(biasB.z, biasB.w) };
        scan8(mk, Wp, acc);
        float c[8];
        unpack2(acc[0], c[0], c[1]); unpack2(acc[1], c[2], c[3]);
        unpack2(acc[2], c[4], c[5]); unpack2(acc[3], c[6], c[7]);

        #pragma unroll
        for (int e = 0; e < 8; e++) {
            v3[e] = 0.5f * (v3[e] + c[e]);
            if (v3[e] >= 1.0f) { v3[e] = 0.f; cnt[e]++; }
        }
        ca = na; cb = nb;
    }

    if (iv) {
        *(float4*)&cnt_sm[grp][8 * lane] =
            make_float4((float)cnt[0], (float)cnt[1], (float)cnt[2], (float)cnt[3]);
        *(float4*)&cnt_sm[grp][8 * lane + 4] =
            make_float4((float)cnt[4], (float)cnt[5], (float)cnt[6], (float)cnt[7]);
    }
    __syncwarp();

    // fused readout + log_softmax (same warp)
    float o = -3.0e38f;
    if (lane < DOUT) {
        float acc = 0.f;
        #pragma unroll 4
        for (int k = 0; k < HID; k++)
            acc += cnt_sm[grp][k] * Wr[k * DOUT + lane];
        o = acc * (1.0f / 101.0f) + br[lane];
    }
    float mx = o;
    #pragma unroll
    for (int off = 16; off; off >>= 1)
        mx = fmaxf(mx, __shfl_xor_sync(0xffffffffu, mx, off));
    float e = (lane < DOUT) ? expf(o - mx) : 0.f;
    float ssum = e;
    #pragma unroll
    for (int off = 16; off; off >>= 1)
        ssum += __shfl_xor_sync(0xffffffffu, ssum, off);
    if (lane < DOUT) out[b * DOUT + lane] = (o - mx) - logf(ssum);
}

// ================= launch ====================================================
extern "C" void kernel_launch(void* const* d_in, const int* in_sizes, int n_in,
                              void* d_out, int out_size) {
    const float* x  = (const float*)d_in[0];
    const float* W1 = (const float*)d_in[1];
    const float* b1 = (const float*)d_in[2];
    const float* W2 = (const float*)d_in[3];
    const float* b2 = (const float*)d_in[4];
    const float* W3 = (const float*)d_in[5];
    const float* b3 = (const float*)d_in[6];
    const float* Wr = (const float*)d_in[7];
    const float* br = (const float*)d_in[8];
    float* out = (float*)d_out;

    cudaFuncSetAttribute(gemm1_mma_kernel, cudaFuncAttributeMaxDynamicSharedMemorySize, GM_SMEM);
    cudaFuncSetAttribute(lif2_kernel,      cudaFuncAttributeMaxDynamicSharedMemorySize, W_SMEM);
    cudaFuncSetAttribute(lif3_kernel,      cudaFuncAttributeMaxDynamicSharedMemorySize, W_SMEM);

    const int grid = 148;

    gemm1_mma_kernel<<<grid, GM_THREADS, GM_SMEM>>>(x, W1, b1);
    lif2_kernel    <<<grid, L_THREADS,   W_SMEM>>>(W2, b2);
    lif3_kernel    <<<grid, L_THREADS,   W_SMEM>>>(W3, b3, Wr, br, out);
}

// round 11
// speedup vs baseline: 1.5507x; 1.1953x over previous
#include <cuda_runtime.h>
#include <cstdint>

#define S_LEN 101
#define BATCH 2048
#define HID 200
#define DIN 120
#define DOUT 12
#define M_TOTAL (S_LEN * BATCH)   // 206848

// Scratch (no allocations allowed -> __device__ globals)
__device__ float g_cur[(size_t)M_TOTAL * HID];        // ~165 MB  cur[b][t][n]

typedef unsigned long long ull;

// ---------- packed f32x2 helpers ----------
__device__ __forceinline__ ull pack2(float lo, float hi) {
    ull r; asm("mov.b64 %0, {%1,%2};" : "=l"(r) : "f"(lo), "f"(hi)); return r;
}
__device__ __forceinline__ void unpack2(ull v, float& lo, float& hi) {
    asm("mov.b64 {%0,%1}, %2;" : "=f"(lo), "=f"(hi) : "l"(v));
}
__device__ __forceinline__ ull add2(ull a, ull b) {
    ull d; asm("add.rn.f32x2 %0, %1, %2;" : "=l"(d) : "l"(a), "l"(b)); return d;
}

// ---------- bf16 / mma / cp.async helpers ----------
__device__ __forceinline__ unsigned bf16x2of(float lo, float hi) {
    unsigned r; asm("cvt.rn.bf16x2.f32 %0, %1, %2;" : "=r"(r) : "f"(hi), "f"(lo));
    return r;   // lo -> bits[0:16), hi -> bits[16:32)
}
__device__ __forceinline__ void bf16_hilo(float x0, float x1, unsigned& h, unsigned& l) {
    h = bf16x2of(x0, x1);
    float h0 = __uint_as_float(h << 16);
    float h1 = __uint_as_float(h & 0xffff0000u);
    l = bf16x2of(x0 - h0, x1 - h1);
}
__device__ __forceinline__ void mma_bf16(float* c,
                                         unsigned a0, unsigned a1, unsigned a2, unsigned a3,
                                         unsigned b0, unsigned b1) {
    asm volatile(
        "mma.sync.aligned.m16n8k16.row.col.f32.bf16.bf16.f32 "
        "{%0,%1,%2,%3}, {%4,%5,%6,%7}, {%8,%9}, {%0,%1,%2,%3};"
        : "+f"(c[0]), "+f"(c[1]), "+f"(c[2]), "+f"(c[3])
        : "r"(a0), "r"(a1), "r"(a2), "r"(a3), "r"(b0), "r"(b1));
}
__device__ __forceinline__ void ldgsts16(unsigned saddr, const void* gptr) {
    asm volatile("cp.async.cg.shared.global [%0], [%1], 16;" :: "r"(saddr), "l"(gptr));
}
#define CPA_COMMIT() asm volatile("cp.async.commit_group;" ::: "memory")
#define CPA_WAIT1()  asm volatile("cp.async.wait_group 1;" ::: "memory")

// ================= Kernel 1: CUR1 = X @ W1 + b1, BF16 3x-split (R10, proven) =
#define GM_THREADS 256
#define NFMAX 13
#define GM_STR 136
#define GM_STG (128 * GM_STR)
#define BF_BYTES (8 * NFMAX * 32 * 16)                 // 53248
#define GM_SMEM (BF_BYTES + 2 * GM_STG * 4)            // 192512 B
#define MTILES (M_TOTAL / 128)                         // 1616

__global__ __launch_bounds__(GM_THREADS, 1)
void gemm1_mma_kernel(const float* __restrict__ x,
                      const float* __restrict__ W1,
                      const float* __restrict__ b1) {
    extern __shared__ char sm[];
    uint4* Bf  = (uint4*)sm;                           // [8][13][32]
    float* As0 = (float*)(sm + BF_BYTES);              // [128][136]
    float* As1 = As0 + GM_STG;

    const int tid   = threadIdx.x;
    const int warp  = tid >> 5;
    const int lane  = tid & 31;
    const int group = lane >> 2;
    const int tg    = lane & 3;
    const int half  = blockIdx.x & 1;
    const int colbase = half ? 104 : 0;
    const int nfc     = half ? 12 : 13;

    const unsigned sA0 = (unsigned)__cvta_generic_to_shared(As0);
    const unsigned sA1 = (unsigned)__cvta_generic_to_shared(As1);

    auto issue_stage = [&](int mt, unsigned sbase) {
        if (mt < MTILES) {
            const int row0 = mt * 128;
            for (int i = tid; i < 128 * 30; i += GM_THREADS) {
                int r = i / 30, cs = i - r * 30;
                int c = cs / 10, j = cs - c * 10;
                int row = row0 + r;
                int b = row / S_LEN, t = row - b * S_LEN;
                const float* gp = x + ((size_t)((b * 3 + c) * S_LEN + t)) * 40 + j * 4;
                unsigned sp = sbase + (unsigned)((r * GM_STR + c * 40 + j * 4) * 4);
                ldgsts16(sp, gp);
            }
        }
        CPA_COMMIT();
    };

    int m = blockIdx.x >> 1;
    issue_stage(m, sA0);

    for (int i = tid; i < 128 * 8 * 2; i += GM_THREADS) {
        int buf = i >> 10, r = (i >> 3) & 127, w = i & 7;
        (buf ? As1 : As0)[r * GM_STR + 120 + w] = 0.f;
    }

    for (int idx = tid; idx < 8 * nfc * 32; idx += GM_THREADS) {
        int ks  = idx / (nfc * 32);
        int rem = idx - ks * nfc * 32;
        int nf  = rem >> 5;
        int t   = rem & 31;
        int g = t >> 2, q = t & 3;
        int n  = colbase + nf * 8 + g;
        int k0 = ks * 16 + 2 * q;
        int k1 = k0 + 8;
        float w00 = W1[k0 * HID + n];
        float w01 = W1[(k0 + 1) * HID + n];
        float w10 = (k1     < DIN) ? W1[k1 * HID + n]       : 0.f;
        float w11 = (k1 + 1 < DIN) ? W1[(k1 + 1) * HID + n] : 0.f;
        unsigned b0h, b0l, b1h, b1l;
        bf16_hilo(w00, w01, b0h, b0l);
        bf16_hilo(w10, w11, b1h, b1l);
        Bf[(ks * NFMAX + nf) * 32 + t] = make_uint4(b0h, b1h, b0l, b1l);
    }

    float2 bias[NFMAX];
    #pragma unroll
    for (int nf = 0; nf < NFMAX; nf++) {
        if (nf < nfc) {
            int c = colbase + nf * 8 + 2 * tg;
            bias[nf] = make_float2(b1[c], b1[c + 1]);
        } else bias[nf] = make_float2(0.f, 0.f);
    }

    int idx = 0;
    for (; m < MTILES; m += 74, idx ^= 1) {
        issue_stage(m + 74, idx ? sA0 : sA1);
        CPA_WAIT1();
        __syncthreads();

        const float* As = idx ? As1 : As0;
        const float* arow  = As + (warp * 16 + group) * GM_STR;
        const float* arow8 = arow + 8 * GM_STR;

        float acc[NFMAX][4];
        #pragma unroll
        for (int nf = 0; nf < NFMAX; nf++) {
            acc[nf][0] = bias[nf].x; acc[nf][1] = bias[nf].y;
            acc[nf][2] = bias[nf].x; acc[nf][3] = bias[nf].y;
        }

        #pragma unroll
        for (int ks = 0; ks < 8; ks++) {
            const int k0 = ks * 16 + 2 * tg;
            float2 p0 = *(const float2*)(arow  + k0);
            float2 p1 = *(const float2*)(arow8 + k0);
            float2 p2 = *(const float2*)(arow  + k0 + 8);
            float2 p3 = *(const float2*)(arow8 + k0 + 8);
            unsigned ah0, al0, ah1, al1, ah2, al2, ah3, al3;
            bf16_hilo(p0.x, p0.y, ah0, al0);
            bf16_hilo(p1.x, p1.y, ah1, al1);
            bf16_hilo(p2.x, p2.y, ah2, al2);
            bf16_hilo(p3.x, p3.y, ah3, al3);

            const uint4* bp = Bf + ks * NFMAX * 32 + lane;
            #pragma unroll
            for (int nf = 0; nf < NFMAX; nf++) {
                if (nf < nfc) {
                    uint4 b = bp[nf * 32];
                    mma_bf16(acc[nf], ah0, ah1, ah2, ah3, b.x, b.y);
                    mma_bf16(acc[nf], ah0, ah1, ah2, ah3, b.z, b.w);
                    mma_bf16(acc[nf], al0, al1, al2, al3, b.x, b.y);
                }
            }
        }

        const int r0 = m * 128 + warp * 16 + group;
        float* op = g_cur + (size_t)r0 * HID + colbase;
        #pragma unroll
        for (int nf = 0; nf < NFMAX; nf++) {
            if (nf < nfc) {
                *(float2*)(op + nf * 8 + 2 * tg) =
                    make_float2(acc[nf][0], acc[nf][1]);
                *(float2*)(op + 8 * HID + nf * 8 + 2 * tg) =
                    make_float2(acc[nf][2], acc[nf][3]);
            }
        }
        __syncthreads();
    }
}

// ========== Kernel 2: FUSED LIF1+L2+LIF2+L3+LIF3+readout (bf16 weights) ======
// 14 warps per CTA, 1 warp = 1 batch element (148*14 = 2072 >= 2048, one pass).
// Lane (lane<25) owns neurons 8*lane..+7. W2/W3 stored bf16 in smem (160 KB):
// one LDS.128 per spike per thread = all 8 neuron weights. s2 masks stay in
// registers (no gmem mask traffic at all).
#define L_GROUPS 14
#define L_THREADS (L_GROUPS * 32)               // 448
#define WROW 100                                // u32 words per bf16 row (200*2B/4)
#define LF_SMEM (2 * HID * HID * 2)             // 160000 B

__device__ __forceinline__ float bfLO(unsigned u) { return __uint_as_float(u << 16); }
__device__ __forceinline__ float bfHI(unsigned u) { return __uint_as_float(u & 0xffff0000u); }

// Warp-uniform sparse scan: 8 bf16 weights per thread per spike (1x LDS.128).
__device__ __forceinline__ void scan8bf(const unsigned* mk, const uint4* Wbase,
                                        int lidx, ull* acc) {
    #pragma unroll
    for (int m = 0; m < 8; m++) {
        unsigned u = mk[m];
        while (u) {                                   // uniform across warp
            int j = __ffs(u) - 1;
            u &= u - 1;
            const uint4 w = Wbase[(8 * j + m) * 25 + lidx];
            acc[0] = add2(acc[0], pack2(bfLO(w.x), bfHI(w.x)));
            acc[1] = add2(acc[1], pack2(bfLO(w.y), bfHI(w.y)));
            acc[2] = add2(acc[2], pack2(bfLO(w.z), bfHI(w.z)));
            acc[3] = add2(acc[3], pack2(bfLO(w.w), bfHI(w.w)));
        }
    }
}

__global__ __launch_bounds__(L_THREADS, 1)
void lif23_kernel(const float* __restrict__ W2, const float* __restrict__ b2,
                  const float* __restrict__ W3, const float* __restrict__ b3,
                  const float* __restrict__ Wr, const float* __restrict__ br,
                  float* __restrict__ out) {
    extern __shared__ unsigned smw[];                  // W2 bf16 [20000 u32] + W3
    uint4* W2b = (uint4*)smw;                          // row h at +h*25 uint4
    uint4* W3b = (uint4*)(smw + HID * HID / 2);
    __shared__ float cnt_sm[L_GROUPS][HID];
    const int tid  = threadIdx.x;
    const int grp  = tid >> 5;
    const int lane = tid & 31;

    // fp32 -> bf16x2 pack (word i = elements 2i, 2i+1; row-major [in][out])
    for (int i = tid; i < HID * HID / 2; i += L_THREADS) {
        float2 a = *(const float2*)(W2 + 2 * i);
        smw[i] = bf16x2of(a.x, a.y);
    }
    for (int i = tid; i < HID * HID / 2; i += L_THREADS) {
        float2 a = *(const float2*)(W3 + 2 * i);
        smw[HID * HID / 2 + i] = bf16x2of(a.x, a.y);
    }

    const bool iv   = (lane < 25);
    const int  lidx = iv ? lane : 0;
    ull bias2[4] = {0,0,0,0}, bias3[4] = {0,0,0,0};
    if (iv) {
        #pragma unroll
        for (int q = 0; q < 4; q++) {
            float2 u2 = *(const float2*)(b2 + 8 * lane + 2 * q);
            float2 u3 = *(const float2*)(b3 + 8 * lane + 2 * q);
            bias2[q] = pack2(u2.x, u2.y);
            bias3[q] = pack2(u3.x, u3.y);
        }
    }
    __syncthreads();

    const int b = blockIdx.x * L_GROUPS + grp;
    if (b >= BATCH) return;                            // warp-uniform

    float v1[8], v2[8], v3[8];
    int cnt[8];
    #pragma unroll
    for (int e = 0; e < 8; e++) { v1[e] = 0.f; v2[e] = 0.f; v3[e] = 0.f; cnt[e] = 0; }
    const float* curb = g_cur + (size_t)b * S_LEN * HID + (iv ? 8 * lane : 0);

    float4 bufA[4], bufB[4];
    #pragma unroll
    for (int q = 0; q < 4; q++) {
        bufA[q] = *(const float4*)(curb + q * HID);
        bufB[q] = *(const float4*)(curb + q * HID + 4);
    }

    for (int t = 0; t < S_LEN; t++) {
        float a[8];
        { float4 ca = bufA[t & 3], cb = bufB[t & 3];
          a[0]=ca.x; a[1]=ca.y; a[2]=ca.z; a[3]=ca.w;
          a[4]=cb.x; a[5]=cb.y; a[6]=cb.z; a[7]=cb.w; }
        int tp = t + 4; if (tp > S_LEN - 1) tp = S_LEN - 1;
        bufA[t & 3] = *(const float4*)(curb + (size_t)tp * HID);
        bufB[t & 3] = *(const float4*)(curb + (size_t)tp * HID + 4);

        // ---- LIF1 ----
        unsigned mk1[8];
        #pragma unroll
        for (int e = 0; e < 8; e++) {
            v1[e] = 0.5f * (v1[e] + a[e]);
            bool s = iv && (v1[e] >= 1.0f);
            if (s) v1[e] = 0.f;
            mk1[e] = __ballot_sync(0xffffffffu, s);
        }

        // ---- layer 2: sparse scan + LIF2 (masks stay in registers) ----
        ull acc[4] = { bias2[0], bias2[1], bias2[2], bias2[3] };
        scan8bf(mk1, W2b, lidx, acc);
        float c[8];
        unpack2(acc[0], c[0], c[1]); unpack2(acc[1], c[2], c[3]);
        unpack2(acc[2], c[4], c[5]); unpack2(acc[3], c[6], c[7]);

        unsigned mk2[8];
        #pragma unroll
        for (int e = 0; e < 8; e++) {
            v2[e] = 0.5f * (v2[e] + c[e]);
            bool s = iv && (v2[e] >= 1.0f);
            if (s) v2[e] = 0.f;
            mk2[e] = __ballot_sync(0xffffffffu, s);
        }

        // ---- layer 3: sparse scan + LIF3 ----
        ull acc3[4] = { bias3[0], bias3[1], bias3[2], bias3[3] };
        scan8bf(mk2, W3b, lidx, acc3);
        float d[8];
        unpack2(acc3[0], d[0], d[1]); unpack2(acc3[1], d[2], d[3]);
        unpack2(acc3[2], d[4], d[5]); unpack2(acc3[3], d[6], d[7]);

        #pragma unroll
        for (int e = 0; e < 8; e++) {
            v3[e] = 0.5f * (v3[e] + d[e]);
            if (v3[e] >= 1.0f) { v3[e] = 0.f; cnt[e]++; }
        }
    }

    if (iv) {
        *(float4*)&cnt_sm[grp][8 * lane] =
            make_float4((float)cnt[0], (float)cnt[1], (float)cnt[2], (float)cnt[3]);
        *(float4*)&cnt_sm[grp][8 * lane + 4] =
            make_float4((float)cnt[4], (float)cnt[5], (float)cnt[6], (float)cnt[7]);
    }
    __syncwarp();

    // fused readout + log_softmax
    float o = -3.0e38f;
    if (lane < DOUT) {
        float acc = 0.f;
        #pragma unroll 4
        for (int k = 0; k < HID; k++)
            acc += cnt_sm[grp][k] * Wr[k * DOUT + lane];
        o = acc * (1.0f / 101.0f) + br[lane];
    }
    float mx = o;
    #pragma unroll
    for (int off = 16; off; off >>= 1)
        mx = fmaxf(mx, __shfl_xor_sync(0xffffffffu, mx, off));
    float e = (lane < DOUT) ? expf(o - mx) : 0.f;
    float ssum = e;
    #pragma unroll
    for (int off = 16; off; off >>= 1)
        ssum += __shfl_xor_sync(0xffffffffu, ssum, off);
    if (lane < DOUT) out[b * DOUT + lane] = (o - mx) - logf(ssum);
}

// ================= launch ====================================================
extern "C" void kernel_launch(void* const* d_in, const int* in_sizes, int n_in,
                              void* d_out, int out_size) {
    const float* x  = (const float*)d_in[0];
    const float* W1 = (const float*)d_in[1];
    const float* b1 = (const float*)d_in[2];
    const float* W2 = (const float*)d_in[3];
    const float* b2 = (const float*)d_in[4];
    const float* W3 = (const float*)d_in[5];
    const float* b3 = (const float*)d_in[6];
    const float* Wr = (const float*)d_in[7];
    const float* br = (const float*)d_in[8];
    float* out = (float*)d_out;

    cudaFuncSetAttribute(gemm1_mma_kernel, cudaFuncAttributeMaxDynamicSharedMemorySize, GM_SMEM);
    cudaFuncSetAttribute(lif23_kernel,     cudaFuncAttributeMaxDynamicSharedMemorySize, LF_SMEM);

    const int grid = 148;

    gemm1_mma_kernel<<<grid, GM_THREADS, GM_SMEM>>>(x, W1, b1);
    lif23_kernel   <<<grid, L_THREADS,   LF_SMEM>>>(W2, b2, W3, b3, Wr, br, out);
}

// round 12
// speedup vs baseline: 1.5645x; 1.0089x over previous
#include <cuda_runtime.h>
#include <cstdint>

#define S_LEN 101
#define BATCH 2048
#define HID 200
#define DIN 120
#define DOUT 12
#define M_TOTAL (S_LEN * BATCH)   // 206848

// Scratch (no allocations allowed -> __device__ globals)
__device__ float g_cur[(size_t)M_TOTAL * HID];        // ~165 MB  cur[b][t][n]

typedef unsigned long long ull;

// ---------- packed f32x2 helpers ----------
__device__ __forceinline__ ull pack2(float lo, float hi) {
    ull r; asm("mov.b64 %0, {%1,%2};" : "=l"(r) : "f"(lo), "f"(hi)); return r;
}
__device__ __forceinline__ void unpack2(ull v, float& lo, float& hi) {
    asm("mov.b64 {%0,%1}, %2;" : "=f"(lo), "=f"(hi) : "l"(v));
}
__device__ __forceinline__ ull add2(ull a, ull b) {
    ull d; asm("add.rn.f32x2 %0, %1, %2;" : "=l"(d) : "l"(a), "l"(b)); return d;
}

// ---------- bf16 / mma / cp.async helpers ----------
__device__ __forceinline__ unsigned bf16x2of(float lo, float hi) {
    unsigned r; asm("cvt.rn.bf16x2.f32 %0, %1, %2;" : "=r"(r) : "f"(hi), "f"(lo));
    return r;   // lo -> bits[0:16), hi -> bits[16:32)
}
__device__ __forceinline__ void bf16_hilo(float x0, float x1, unsigned& h, unsigned& l) {
    h = bf16x2of(x0, x1);
    float h0 = __uint_as_float(h << 16);
    float h1 = __uint_as_float(h & 0xffff0000u);
    l = bf16x2of(x0 - h0, x1 - h1);
}
__device__ __forceinline__ void mma_bf16(float* c,
                                         unsigned a0, unsigned a1, unsigned a2, unsigned a3,
                                         unsigned b0, unsigned b1) {
    asm volatile(
        "mma.sync.aligned.m16n8k16.row.col.f32.bf16.bf16.f32 "
        "{%0,%1,%2,%3}, {%4,%5,%6,%7}, {%8,%9}, {%0,%1,%2,%3};"
        : "+f"(c[0]), "+f"(c[1]), "+f"(c[2]), "+f"(c[3])
        : "r"(a0), "r"(a1), "r"(a2), "r"(a3), "r"(b0), "r"(b1));
}
__device__ __forceinline__ void ldgsts16(unsigned saddr, const void* gptr) {
    asm volatile("cp.async.cg.shared.global [%0], [%1], 16;" :: "r"(saddr), "l"(gptr));
}
#define CPA_COMMIT() asm volatile("cp.async.commit_group;" ::: "memory")
#define CPA_WAIT1()  asm volatile("cp.async.wait_group 1;" ::: "memory")

// ================= Kernel 1: CUR1 = X @ W1 + b1, BF16 3x-split ==============
#define GM_THREADS 256
#define NFMAX 13
#define GM_STR 136
#define GM_STG (128 * GM_STR)
#define BF_BYTES (8 * NFMAX * 32 * 16)                 // 53248
#define GM_SMEM (BF_BYTES + 2 * GM_STG * 4)            // 192512 B
#define MTILES (M_TOTAL / 128)                         // 1616

__global__ __launch_bounds__(GM_THREADS, 1)
void gemm1_mma_kernel(const float* __restrict__ x,
                      const float* __restrict__ W1,
                      const float* __restrict__ b1) {
    extern __shared__ char sm[];
    uint4* Bf  = (uint4*)sm;                           // [8][13][32]
    float* As0 = (float*)(sm + BF_BYTES);              // [128][136]
    float* As1 = As0 + GM_STG;

    const int tid   = threadIdx.x;
    const int warp  = tid >> 5;
    const int lane  = tid & 31;
    const int group = lane >> 2;
    const int tg    = lane & 3;
    const int half  = blockIdx.x & 1;
    const int colbase = half ? 104 : 0;
    const int nfc     = half ? 12 : 13;

    const unsigned sA0 = (unsigned)__cvta_generic_to_shared(As0);
    const unsigned sA1 = (unsigned)__cvta_generic_to_shared(As1);

    auto issue_stage = [&](int mt, unsigned sbase) {
        if (mt < MTILES) {
            const int row0 = mt * 128;
            for (int i = tid; i < 128 * 30; i += GM_THREADS) {
                int r = i / 30, cs = i - r * 30;
                int c = cs / 10, j = cs - c * 10;
                int row = row0 + r;
                int b = row / S_LEN, t = row - b * S_LEN;
                const float* gp = x + ((size_t)((b * 3 + c) * S_LEN + t)) * 40 + j * 4;
                unsigned sp = sbase + (unsigned)((r * GM_STR + c * 40 + j * 4) * 4);
                ldgsts16(sp, gp);
            }
        }
        CPA_COMMIT();
    };

    int m = blockIdx.x >> 1;
    issue_stage(m, sA0);

    for (int i = tid; i < 128 * 8 * 2; i += GM_THREADS) {
        int buf = i >> 10, r = (i >> 3) & 127, w = i & 7;
        (buf ? As1 : As0)[r * GM_STR + 120 + w] = 0.f;
    }

    for (int idx = tid; idx < 8 * nfc * 32; idx += GM_THREADS) {
        int ks  = idx / (nfc * 32);
        int rem = idx - ks * nfc * 32;
        int nf  = rem >> 5;
        int t   = rem & 31;
        int g = t >> 2, q = t & 3;
        int n  = colbase + nf * 8 + g;
        int k0 = ks * 16 + 2 * q;
        int k1 = k0 + 8;
        float w00 = W1[k0 * HID + n];
        float w01 = W1[(k0 + 1) * HID + n];
        float w10 = (k1     < DIN) ? W1[k1 * HID + n]       : 0.f;
        float w11 = (k1 + 1 < DIN) ? W1[(k1 + 1) * HID + n] : 0.f;
        unsigned b0h, b0l, b1h, b1l;
        bf16_hilo(w00, w01, b0h, b0l);
        bf16_hilo(w10, w11, b1h, b1l);
        Bf[(ks * NFMAX + nf) * 32 + t] = make_uint4(b0h, b1h, b0l, b1l);
    }

    float2 bias[NFMAX];
    #pragma unroll
    for (int nf = 0; nf < NFMAX; nf++) {
        if (nf < nfc) {
            int c = colbase + nf * 8 + 2 * tg;
            bias[nf] = make_float2(b1[c], b1[c + 1]);
        } else bias[nf] = make_float2(0.f, 0.f);
    }

    int idx = 0;
    for (; m < MTILES; m += 74, idx ^= 1) {
        issue_stage(m + 74, idx ? sA0 : sA1);
        CPA_WAIT1();
        __syncthreads();

        const float* As = idx ? As1 : As0;
        const float* arow  = As + (warp * 16 + group) * GM_STR;
        const float* arow8 = arow + 8 * GM_STR;

        float acc[NFMAX][4];
        #pragma unroll
        for (int nf = 0; nf < NFMAX; nf++) {
            acc[nf][0] = bias[nf].x; acc[nf][1] = bias[nf].y;
            acc[nf][2] = bias[nf].x; acc[nf][3] = bias[nf].y;
        }

        #pragma unroll
        for (int ks = 0; ks < 8; ks++) {
            const int k0 = ks * 16 + 2 * tg;
            float2 p0 = *(const float2*)(arow  + k0);
            float2 p1 = *(const float2*)(arow8 + k0);
            float2 p2 = *(const float2*)(arow  + k0 + 8);
            float2 p3 = *(const float2*)(arow8 + k0 + 8);
            unsigned ah0, al0, ah1, al1, ah2, al2, ah3, al3;
            bf16_hilo(p0.x, p0.y, ah0, al0);
            bf16_hilo(p1.x, p1.y, ah1, al1);
            bf16_hilo(p2.x, p2.y, ah2, al2);
            bf16_hilo(p3.x, p3.y, ah3, al3);

            const uint4* bp = Bf + ks * NFMAX * 32 + lane;
            // nf pairs interleaved -> doubled accumulator-chain spacing
            #pragma unroll
            for (int p = 0; p < 6; p++) {
                const int n0 = 2 * p, n1 = 2 * p + 1;
                uint4 bA = bp[n0 * 32];                       // LDS.128
                uint4 bB = bp[n1 * 32];
                mma_bf16(acc[n0], ah0, ah1, ah2, ah3, bA.x, bA.y);
                mma_bf16(acc[n1], ah0, ah1, ah2, ah3, bB.x, bB.y);
                mma_bf16(acc[n0], ah0, ah1, ah2, ah3, bA.z, bA.w);
                mma_bf16(acc[n1], ah0, ah1, ah2, ah3, bB.z, bB.w);
                mma_bf16(acc[n0], al0, al1, al2, al3, bA.x, bA.y);
                mma_bf16(acc[n1], al0, al1, al2, al3, bB.x, bB.y);
            }
            if (nfc & 1) {                                    // nf = 12 (even CTAs)
                uint4 b = bp[12 * 32];
                mma_bf16(acc[12], ah0, ah1, ah2, ah3, b.x, b.y);
                mma_bf16(acc[12], ah0, ah1, ah2, ah3, b.z, b.w);
                mma_bf16(acc[12], al0, al1, al2, al3, b.x, b.y);
            }
        }

        const int r0 = m * 128 + warp * 16 + group;
        float* op = g_cur + (size_t)r0 * HID + colbase;
        #pragma unroll
        for (int nf = 0; nf < NFMAX; nf++) {
            if (nf < nfc) {
                *(float2*)(op + nf * 8 + 2 * tg) =
                    make_float2(acc[nf][0], acc[nf][1]);
                *(float2*)(op + 8 * HID + nf * 8 + 2 * tg) =
                    make_float2(acc[nf][2], acc[nf][3]);
            }
        }
        __syncthreads();
    }
}

// ========== Kernel 2: FUSED LIF1+L2+LIF2+L3+LIF3+readout (bf16 weights) ======
// 14 warps/CTA, warp = batch element. Lane (lane<25) owns neurons 8L..8L+7.
// W2/W3 bf16 in smem with a 201st all-zero row (index 200) so the spike scan
// can process 2 spikes per iteration branch-free (invalid slot -> zero row).
#define L_GROUPS 14
#define L_THREADS (L_GROUPS * 32)               // 448
#define LROWS 201
#define LSTRIDE (LROWS * 100)                   // u32 words per layer (20100)
#define LF_SMEM (2 * LSTRIDE * 4)               // 160800 B

__device__ __forceinline__ float bfLO(unsigned u) { return __uint_as_float(u << 16); }
__device__ __forceinline__ float bfHI(unsigned u) { return __uint_as_float(u & 0xffff0000u); }

// Warp-uniform sparse scan, 2 spikes per iteration (2nd slot -> zero row 200).
__device__ __forceinline__ void scan8bf(const unsigned* mk, const uint4* Wbase,
                                        int lidx, ull* acc) {
    #pragma unroll
    for (int m = 0; m < 8; m++) {
        unsigned u = mk[m];
        while (u) {                                   // uniform across warp
            int j0 = __ffs(u) - 1;
            u &= u - 1;
            int j1 = __ffs(u);                        // 0 if empty
            int h0 = 8 * j0 + m;
            int h1 = j1 ? 8 * (j1 - 1) + m : 200;     // 200 = zero row
            u = j1 ? (u & (u - 1)) : 0u;
            const uint4 w0 = Wbase[h0 * 25 + lidx];
            const uint4 w1 = Wbase[h1 * 25 + lidx];
            acc[0] = add2(acc[0], pack2(bfLO(w0.x), bfHI(w0.x)));
            acc[1] = add2(acc[1], pack2(bfLO(w0.y), bfHI(w0.y)));
            acc[2] = add2(acc[2], pack2(bfLO(w0.z), bfHI(w0.z)));
            acc[3] = add2(acc[3], pack2(bfLO(w0.w), bfHI(w0.w)));
            acc[0] = add2(acc[0], pack2(bfLO(w1.x), bfHI(w1.x)));
            acc[1] = add2(acc[1], pack2(bfLO(w1.y), bfHI(w1.y)));
            acc[2] = add2(acc[2], pack2(bfLO(w1.z), bfHI(w1.z)));
            acc[3] = add2(acc[3], pack2(bfLO(w1.w), bfHI(w1.w)));
        }
    }
}

__global__ __launch_bounds__(L_THREADS, 1)
void lif23_kernel(const float* __restrict__ W2, const float* __restrict__ b2,
                  const float* __restrict__ W3, const float* __restrict__ b3,
                  const float* __restrict__ Wr, const float* __restrict__ br,
                  float* __restrict__ out) {
    extern __shared__ unsigned smw[];                  // [2][201 rows x 100 u32]
    uint4* W2b = (uint4*)smw;                          // row h at +h*25 uint4
    uint4* W3b = (uint4*)(smw + LSTRIDE);
    __shared__ float cnt_sm[L_GROUPS][HID];
    const int tid  = threadIdx.x;
    const int grp  = tid >> 5;
    const int lane = tid & 31;

    // fp32 -> bf16x2 pack; rows 0..199 = weights, row 200 = zeros
    for (int i = tid; i < HID * HID / 2; i += L_THREADS) {
        float2 a2 = *(const float2*)(W2 + 2 * i);
        float2 a3 = *(const float2*)(W3 + 2 * i);
        smw[i]           = bf16x2of(a2.x, a2.y);
        smw[LSTRIDE + i] = bf16x2of(a3.x, a3.y);
    }
    for (int i = tid; i < 100; i += L_THREADS) {
        smw[HID * HID / 2 + i]           = 0u;         // W2 zero row
        smw[LSTRIDE + HID * HID / 2 + i] = 0u;         // W3 zero row
    }

    const bool iv   = (lane < 25);
    const int  lidx = iv ? lane : 0;
    ull bias2[4] = {0,0,0,0}, bias3[4] = {0,0,0,0};
    if (iv) {
        #pragma unroll
        for (int q = 0; q < 4; q++) {
            float2 u2 = *(const float2*)(b2 + 8 * lane + 2 * q);
            float2 u3 = *(const float2*)(b3 + 8 * lane + 2 * q);
            bias2[q] = pack2(u2.x, u2.y);
            bias3[q] = pack2(u3.x, u3.y);
        }
    }
    __syncthreads();

    const int b = blockIdx.x * L_GROUPS + grp;
    if (b >= BATCH) return;                            // warp-uniform

    float v1[8], v2[8], v3[8];
    int cnt[8];
    #pragma unroll
    for (int e = 0; e < 8; e++) { v1[e] = 0.f; v2[e] = 0.f; v3[e] = 0.f; cnt[e] = 0; }
    const float* curb = g_cur + (size_t)b * S_LEN * HID + (iv ? 8 * lane : 0);

    float4 bufA[4], bufB[4];
    #pragma unroll
    for (int q = 0; q < 4; q++) {
        bufA[q] = *(const float4*)(curb + q * HID);
        bufB[q] = *(const float4*)(curb + q * HID + 4);
    }

    for (int t = 0; t < S_LEN; t++) {
        float a[8];
        { float4 ca = bufA[t & 3], cb = bufB[t & 3];
          a[0]=ca.x; a[1]=ca.y; a[2]=ca.z; a[3]=ca.w;
          a[4]=cb.x; a[5]=cb.y; a[6]=cb.z; a[7]=cb.w; }
        int tp = t + 4; if (tp > S_LEN - 1) tp = S_LEN - 1;
        bufA[t & 3] = *(const float4*)(curb + (size_t)tp * HID);
        bufB[t & 3] = *(const float4*)(curb + (size_t)tp * HID + 4);

        // ---- LIF1 ----
        unsigned mk1[8];
        #pragma unroll
        for (int e = 0; e < 8; e++) {
            v1[e] = 0.5f * (v1[e] + a[e]);
            bool s = iv && (v1[e] >= 1.0f);
            if (s) v1[e] = 0.f;
            mk1[e] = __ballot_sync(0xffffffffu, s);
        }

        // ---- layer 2: sparse scan + LIF2 ----
        ull acc[4] = { bias2[0], bias2[1], bias2[2], bias2[3] };
        scan8bf(mk1, W2b, lidx, acc);
        float c[8];
        unpack2(acc[0], c[0], c[1]); unpack2(acc[1], c[2], c[3]);
        unpack2(acc[2], c[4], c[5]); unpack2(acc[3], c[6], c[7]);

        unsigned mk2[8];
        #pragma unroll
        for (int e = 0; e < 8; e++) {
            v2[e] = 0.5f * (v2[e] + c[e]);
            bool s = iv && (v2[e] >= 1.0f);
            if (s) v2[e] = 0.f;
            mk2[e] = __ballot_sync(0xffffffffu, s);
        }

        // ---- layer 3: sparse scan + LIF3 ----
        ull acc3[4] = { bias3[0], bias3[1], bias3[2], bias3[3] };
        scan8bf(mk2, W3b, lidx, acc3);
        float d[8];
        unpack2(acc3[0], d[0], d[1]); unpack2(acc3[1], d[2], d[3]);
        unpack2(acc3[2], d[4], d[5]); unpack2(acc3[3], d[6], d[7]);

        #pragma unroll
        for (int e = 0; e < 8; e++) {
            v3[e] = 0.5f * (v3[e] + d[e]);
            if (v3[e] >= 1.0f) { v3[e] = 0.f; cnt[e]++; }
        }
    }

    if (iv) {
        *(float4*)&cnt_sm[grp][8 * lane] =
            make_float4((float)cnt[0], (float)cnt[1], (float)cnt[2], (float)cnt[3]);
        *(float4*)&cnt_sm[grp][8 * lane + 4] =
            make_float4((float)cnt[4], (float)cnt[5], (float)cnt[6], (float)cnt[7]);
    }
    __syncwarp();

    // fused readout + log_softmax
    float o = -3.0e38f;
    if (lane < DOUT) {
        float acc = 0.f;
        #pragma unroll 4
        for (int k = 0; k < HID; k++)
            acc += cnt_sm[grp][k] * Wr[k * DOUT + lane];
        o = acc * (1.0f / 101.0f) + br[lane];
    }
    float mx = o;
    #pragma unroll
    for (int off = 16; off; off >>= 1)
        mx = fmaxf(mx, __shfl_xor_sync(0xffffffffu, mx, off));
    float e = (lane < DOUT) ? expf(o - mx) : 0.f;
    float ssum = e;
    #pragma unroll
    for (int off = 16; off; off >>= 1)
        ssum += __shfl_xor_sync(0xffffffffu, ssum, off);
    if (lane < DOUT) out[b * DOUT + lane] = (o - mx) - logf(ssum);
}

// ================= launch ====================================================
extern "C" void kernel_launch(void* const* d_in, const int* in_sizes, int n_in,
                              void* d_out, int out_size) {
    const float* x  = (const float*)d_in[0];
    const float* W1 = (const float*)d_in[1];
    const float* b1 = (const float*)d_in[2];
    const float* W2 = (const float*)d_in[3];
    const float* b2 = (const float*)d_in[4];
    const float* W3 = (const float*)d_in[5];
    const float* b3 = (const float*)d_in[6];
    const float* Wr = (const float*)d_in[7];
    const float* br = (const float*)d_in[8];
    float* out = (float*)d_out;

    cudaFuncSetAttribute(gemm1_mma_kernel, cudaFuncAttributeMaxDynamicSharedMemorySize, GM_SMEM);
    cudaFuncSetAttribute(lif23_kernel,     cudaFuncAttributeMaxDynamicSharedMemorySize, LF_SMEM);

    const int grid = 148;

    gemm1_mma_kernel<<<grid, GM_THREADS, GM_SMEM>>>(x, W1, b1);
    lif23_kernel   <<<grid, L_THREADS,   LF_SMEM>>>(W2, b2, W3, b3, Wr, br, out);
}